// round 13
// baseline (speedup 1.0000x reference)
#include <cuda_runtime.h>
#include <cuda_bf16.h>
#include <cstdint>

typedef __nv_bfloat16 bf16;

#define Bc   16
#define Cc   256
#define Sc   4096
#define Lc   256
#define Ec   256

// ---------------- scratch (device globals; no allocation allowed) -----------
__device__ bf16  g_q [Bc * Sc * Ec];       // Q projection, bf16
__device__ bf16  g_k [Bc * Lc * Ec];       // K projection, bf16
__device__ bf16  g_v [Bc * Lc * Ec];       // V projection, bf16
__device__ bf16  g_o [Bc * Sc * Ec];       // attention output, bf16
__device__ bf16  g_kn[Bc * Lc * Cc];       // LN(refs), bf16
__device__ uint32_t g_wfrag[4 * 65536];    // fragment-ordered weight images q,k,v,o
__device__ float g_mod[Bc * 3 * Cc];       // shift|scale|gate per batch
__device__ float g_kbias[Bc * Lc];         // 0 or -1e30

// ---------------- small asm helpers ------------------------------------------
__device__ __forceinline__ uint32_t smem_u32(const void* p) {
    uint32_t a;
    asm("{ .reg .u64 t; cvta.to.shared.u64 t, %1; cvt.u32.u64 %0, t; }" : "=r"(a) : "l"(p));
    return a;
}
__device__ __forceinline__ float ex2(float x) {
    float y; asm("ex2.approx.ftz.f32 %0, %1;" : "=f"(y) : "f"(x)); return y;
}
__device__ __forceinline__ uint32_t packbf(float lo, float hi) {
    uint32_t d; asm("cvt.rn.bf16x2.f32 %0, %1, %2;" : "=r"(d) : "f"(hi), "f"(lo)); return d;
}
__device__ __forceinline__ void ldsm4(uint32_t* r, uint32_t a) {
    asm volatile("ldmatrix.sync.aligned.m8n8.x4.shared.b16 {%0,%1,%2,%3}, [%4];"
                 : "=r"(r[0]), "=r"(r[1]), "=r"(r[2]), "=r"(r[3]) : "r"(a));
}
__device__ __forceinline__ void ldsm4t(uint32_t* r, uint32_t a) {
    asm volatile("ldmatrix.sync.aligned.m8n8.x4.trans.shared.b16 {%0,%1,%2,%3}, [%4];"
                 : "=r"(r[0]), "=r"(r[1]), "=r"(r[2]), "=r"(r[3]) : "r"(a));
}
__device__ __forceinline__ void mma16816(float* d, const uint32_t* a, const uint32_t* b) {
    asm volatile("mma.sync.aligned.m16n8k16.row.col.f32.bf16.bf16.f32 "
                 "{%0,%1,%2,%3},{%4,%5,%6,%7},{%8,%9},{%0,%1,%2,%3};"
                 : "+f"(d[0]), "+f"(d[1]), "+f"(d[2]), "+f"(d[3])
                 : "r"(a[0]), "r"(a[1]), "r"(a[2]), "r"(a[3]), "r"(b[0]), "r"(b[1]));
}

// ============ fused prep: mask | lnref | mod | weight-fragment gen ===========
// grid: [0] mask, [1..512] lnref, [513..560] mod, [561..1584] wfrag
__global__ void prep_kernel(const void* masks,
                            const float* wq, const float* wk,
                            const float* wv, const float* wo,
                            const float* refs, const float* lw_t, const float* lb_t,
                            const float* re, const float* Wada, const float* bada) {
    __shared__ char shbuf[33312];
    int blk = blockIdx.x, tid = threadIdx.x;

    if (blk == 0) {
        int* flags = (int*)shbuf;
        if (tid == 0) { flags[0] = 0; flags[1] = 0; flags[2] = 0; }
        __syncthreads();
        const unsigned char* mb = (const unsigned char*)masks;
        const float*         mf = (const float*)masks;
        const int*           mi = (const int*)masks;
        for (int i = tid; i < 1024; i += 256) {
            float f = mf[i];
            if (!(f == 0.f || f == 1.f)) flags[0] = 1;
            if (f == 1.f) flags[1] = 1;
        }
        for (int i = tid; i < Bc * Lc; i += 256)
            if ((i & 3) && mb[i]) flags[2] = 1;
        __syncthreads();
        bool isf = (!flags[0]) && flags[1];
        bool isu8 = flags[2];
        for (int i = tid; i < Bc * Lc; i += 256) {
            int m;
            if (isf)       m = (mf[i] != 0.f);
            else if (isu8) m = mb[i];
            else           m = mi[i];
            g_kbias[i] = m ? -1e30f : 0.f;
        }
    } else if (blk <= 512) {
        int lane = tid & 31, w = tid >> 5;
        int row = (blk - 1) * 8 + w;
        const float* rr = refs + (size_t)row * 256;
        float v[8], s = 0.f, s2 = 0.f;
#pragma unroll
        for (int i = 0; i < 8; i++) {
            v[i] = rr[lane + 32 * i];
            s += v[i]; s2 += v[i] * v[i];
        }
#pragma unroll
        for (int o = 16; o; o >>= 1) {
            s  += __shfl_xor_sync(~0u, s,  o);
            s2 += __shfl_xor_sync(~0u, s2, o);
        }
        float mu = s * (1.f / 256.f);
        float rs = rsqrtf(s2 * (1.f / 256.f) - mu * mu + 1e-5f);
#pragma unroll
        for (int i = 0; i < 8; i++) {
            int c = lane + 32 * i;
            g_kn[(size_t)row * 256 + c] = __float2bfloat16((v[i] - mu) * rs * lw_t[c] + lb_t[c]);
        }
    } else if (blk <= 560) {
        float* sv = (float*)shbuf;                 // [16][264]
        float* wt = (float*)(shbuf + 16896);       // [256][16]
        int c0 = (blk - 513) * 16;
        for (int u = tid; u < 4096; u += 256) {
            float x = re[u];
            sv[(u >> 8) * 264 + (u & 255)] = x / (1.f + __expf(-x));
        }
        for (int u = tid; u < 4096; u += 256) {
            int k = u >> 4, c = u & 15;
            wt[k * 16 + c] = Wada[(size_t)k * 768 + c0 + c];
        }
        __syncthreads();
        int b = tid >> 4, c = tid & 15;
        const float* svb = sv + b * 264;
        float acc = bada[c0 + c];
#pragma unroll 8
        for (int k = 0; k < 256; k++) acc = fmaf(svb[k], wt[k * 16 + c], acc);
        g_mod[b * 768 + c0 + c] = acc;
    } else {
        // ---- weight fragment image generation ----
        // u decode: j=u&3, n2=(u>>2)&3, lane=(u>>4)&31, wn=(u>>9)&3, k16=u>>11
        int f = blk - 561;
        int widx = f >> 8, chunk = f & 255;
        const float* W[4] = {wq, wk, wv, wo};
        const float* Ws = W[widx];
        int u = chunk * 256 + tid;
        int j    = u & 3;
        int n2   = (u >> 2) & 3;
        int lane = (u >> 4) & 31;
        int wn   = (u >> 9) & 3;
        int k16  = u >> 11;
        int n = wn * 64 + n2 * 16 + ((j & 2) ? 8 : 0) + (lane >> 2);
        int k = k16 * 16 + 2 * (lane & 3) + ((j & 1) ? 8 : 0);
        float w0 = Ws[(size_t)k * 256 + n];
        float w1 = Ws[(size_t)(k + 1) * 256 + n];
        g_wfrag[widx * 65536 + u] = packbf(w0, w1);
    }
}

// ====== raw-mma GEMM core: 64x256x256, B fragments via LDG (no weight smem) ==
// 8 warps = 2(m) x 4(n); warp tile 32x64; acc[2][8][4]; zero barriers in k-loop.
__device__ __forceinline__ void mma_gemm64(uint32_t sA, const uint4* pW, int tid,
                                           float acc[2][8][4]) {
    int w = tid >> 5, lane = tid & 31;
    int wm = w >> 2, wn = w & 3;
    uint32_t aBase = sA + (uint32_t)(((wm * 32 + (lane & 15)) * 264 + (lane >> 4) * 8) * 2);
    const uint4* pB = pW + (wn * 32 + lane) * 4;
    uint4 Bb[2][4];
#pragma unroll
    for (int j = 0; j < 4; j++) Bb[0][j] = pB[j];
#pragma unroll
    for (int k16 = 0; k16 < 16; k16++) {
        int cur = k16 & 1;
        if (k16 < 15) {
            const uint4* pn = pB + (k16 + 1) * 512;
#pragma unroll
            for (int j = 0; j < 4; j++) Bb[cur ^ 1][j] = pn[j];
        }
        uint32_t Af[2][4];
#pragma unroll
        for (int m = 0; m < 2; m++)
            ldsm4(Af[m], aBase + (uint32_t)((m * 16 * 264 + k16 * 16) * 2));
#pragma unroll
        for (int n2 = 0; n2 < 4; n2++) {
            uint32_t bf[4] = {Bb[cur][n2].x, Bb[cur][n2].y, Bb[cur][n2].z, Bb[cur][n2].w};
#pragma unroll
            for (int m = 0; m < 2; m++) {
                mma16816(acc[m][2 * n2],     Af[m], bf);
                mma16816(acc[m][2 * n2 + 1], Af[m], bf + 2);
            }
        }
    }
}

// direct-from-register bf16 epilogue: acc + bias -> dst[row][256]
__device__ __forceinline__ void epilogue_bf16(float acc[2][8][4], const float* sB,
                                              bf16* dst, int tid) {
    int w = tid >> 5, lane = tid & 31;
    int wm = w >> 2, wn = w & 3;
    int r0 = wm * 32 + (lane >> 2);
    int cb0 = wn * 64 + 2 * (lane & 3);
#pragma unroll
    for (int m = 0; m < 2; m++) {
        int row = r0 + m * 16;
#pragma unroll
        for (int n = 0; n < 8; n++) {
            int cb = cb0 + (n >> 1) * 16 + (n & 1) * 8;
            float bx = sB[cb], by = sB[cb + 1];
            *(uint32_t*)(dst + (size_t)row * 256 + cb) =
                packbf(acc[m][n][0] + bx, acc[m][n][1] + by);
            *(uint32_t*)(dst + (size_t)(row + 8) * 256 + cb) =
                packbf(acc[m][n][2] + bx, acc[m][n][3] + by);
        }
    }
}

// ---- merged Q + K/V projection ----------------------------------------------
// smem: As 33792 | Xf[32][261] 33408@33792 | lw@67200 lb@68224 sB@69248 = 70272
__global__ void __launch_bounds__(256, 2)
qkvproj_kernel(const float* img, const float* lnw, const float* lnb,
               const float* bq, const float* bk, const float* bv) {
    extern __shared__ char smem[];
    bf16*  As = (bf16*)smem;
    float* Xf = (float*)(smem + 33792);
    float* lw = (float*)(smem + 67200);
    float* lb = (float*)(smem + 68224);
    float* sB = (float*)(smem + 69248);

    int tid = threadIdx.x, blk = blockIdx.x;
    int w = tid >> 5, lane = tid & 31;

    if (blk < 1024) {
        int b = blk >> 6, s0 = (blk & 63) << 6;
        lw[tid] = lnw[tid]; lb[tid] = lnb[tid]; sB[tid] = bq[tid];

        for (int g = 0; g < 2; g++) {
            for (int i = 0; i < 32; i++) {
                int c = w + 8 * i;
                Xf[lane * 261 + c] = img[((size_t)(b * 256 + c)) * 4096 + s0 + g * 32 + lane];
            }
            __syncthreads();
            for (int j = 0; j < 4; j++) {
                int rl = w * 4 + j;
                float v[8], s = 0.f, s2 = 0.f;
#pragma unroll
                for (int i = 0; i < 8; i++) {
                    v[i] = Xf[rl * 261 + lane + 32 * i];
                    s += v[i]; s2 += v[i] * v[i];
                }
#pragma unroll
                for (int o = 16; o; o >>= 1) {
                    s  += __shfl_xor_sync(~0u, s,  o);
                    s2 += __shfl_xor_sync(~0u, s2, o);
                }
                float mu = s * (1.f / 256.f);
                float rs = rsqrtf(s2 * (1.f / 256.f) - mu * mu + 1e-5f);
                int R = g * 32 + rl;
#pragma unroll
                for (int i = 0; i < 8; i++) {
                    int c = lane + 32 * i;
                    As[R * 264 + c] = __float2bfloat16((v[i] - mu) * rs * lw[c] + lb[c]);
                }
            }
            __syncthreads();
        }

        float acc[2][8][4];
#pragma unroll
        for (int m = 0; m < 2; m++)
#pragma unroll
            for (int n = 0; n < 8; n++)
#pragma unroll
                for (int q = 0; q < 4; q++) acc[m][n][q] = 0.f;
        mma_gemm64(smem_u32(As), (const uint4*)g_wfrag, tid, acc);
        epilogue_bf16(acc, sB, g_q + (size_t)blk * 64 * 256, tid);
    } else {
        int blk2 = blk - 1024;
        int which = blk2 >> 6, chunk = blk2 & 63;
        sB[tid] = which ? bv[tid] : bk[tid];
        {
            const uint4* src = (const uint4*)(g_kn + (size_t)chunk * 64 * 256);
            for (int u = tid; u < 2048; u += 256) {
                int row = u >> 5, j = u & 31;
                *((uint4*)(As + row * 264) + j) = src[row * 32 + j];
            }
        }
        __syncthreads();

        float acc[2][8][4];
#pragma unroll
        for (int m = 0; m < 2; m++)
#pragma unroll
            for (int n = 0; n < 8; n++)
#pragma unroll
                for (int q = 0; q < 4; q++) acc[m][n][q] = 0.f;
        mma_gemm64(smem_u32(As), (const uint4*)(g_wfrag + (1 + which) * 65536), tid, acc);
        epilogue_bf16(acc, sB, (which ? g_v : g_k) + (size_t)chunk * 64 * 256, tid);
    }
}

// ------- flash attention: 256 q/block, 32-row warp tiles, K double-buffer ----
// smem: Ks[256][72] 36864 | Vs[256][72] 36864@36864 | B2[256] 1024@73728 = 74752
__global__ void __launch_bounds__(256, 1) attn_kernel() {
    extern __shared__ char smem[];
    bf16*  Ks = (bf16*)smem;
    bf16*  Vs = (bf16*)(smem + 36864);
    float* B2 = (float*)(smem + 73728);

    int tid = threadIdx.x, w = tid >> 5, lane = tid & 31;
    int s0 = blockIdx.x * 256, h = blockIdx.y, b = blockIdx.z;

    const bf16* ksrc = g_k + ((size_t)(b * 256)) * 256 + h * 64;
    const bf16* vsrc = g_v + ((size_t)(b * 256)) * 256 + h * 64;
    for (int u = tid; u < 2048; u += 256) {
        int r = u >> 3, j = u & 7;
        *(uint4*)(Ks + r * 72 + j * 8) = *(const uint4*)(ksrc + (size_t)r * 256 + j * 8);
        *(uint4*)(Vs + r * 72 + j * 8) = *(const uint4*)(vsrc + (size_t)r * 256 + j * 8);
    }
    B2[tid] = g_kbias[b * 256 + tid] * 1.44269504f;

    int rq = lane >> 2, c0 = 2 * (lane & 3);
    uint32_t A[2][4][4];
#pragma unroll
    for (int g = 0; g < 2; g++) {
        const bf16* q0 = g_q + ((size_t)(b * 4096 + s0 + w * 32 + g * 16 + rq)) * 256 + h * 64;
        const bf16* q1 = q0 + 8 * 256;
#pragma unroll
        for (int kk = 0; kk < 4; kk++) {
            A[g][kk][0] = *(const uint32_t*)(q0 + kk * 16 + c0);
            A[g][kk][1] = *(const uint32_t*)(q1 + kk * 16 + c0);
            A[g][kk][2] = *(const uint32_t*)(q0 + kk * 16 + c0 + 8);
            A[g][kk][3] = *(const uint32_t*)(q1 + kk * 16 + c0 + 8);
        }
    }
    __syncthreads();

    uint32_t sbK = smem_u32(Ks), sbV = smem_u32(Vs);
    int nrow_off = ((lane >> 4) & 1) * 8 + (lane & 7);
    int koff     = ((lane >> 3) & 1) * 8;
    uint32_t kbaseL = sbK + (uint32_t)(nrow_off * 72 + koff) * 2;
    int krow_off = ((lane >> 3) & 1) * 8 + (lane & 7);
    int ncol_off = ((lane >> 4) & 1) * 8;
    uint32_t vbaseL = sbV + (uint32_t)(krow_off * 72 + ncol_off) * 2;

    const float SCL2 = 0.125f * 1.44269504f;
    float O[2][8][4];
#pragma unroll
    for (int g = 0; g < 2; g++)
#pragma unroll
        for (int t = 0; t < 8; t++)
#pragma unroll
            for (int q = 0; q < 4; q++) O[g][t][q] = 0.f;
    float l0[2] = {0.f, 0.f}, l1[2] = {0.f, 0.f};

    uint32_t kb[2][4][4];
#pragma unroll
    for (int kk = 0; kk < 4; kk++)
        ldsm4(kb[0][kk], kbaseL + (uint32_t)((kk * 16) * 2));

    uint32_t pa[2][4];
#pragma unroll
    for (int s = 0; s < 16; s++) {
        int cur = s & 1, nxt = cur ^ 1;
        int kb0 = s * 16;
        float S[2][2][4];
#pragma unroll
        for (int g = 0; g < 2; g++) {
#pragma unroll
            for (int q = 0; q < 4; q++) { S[g][0][q] = 0.f; S[g][1][q] = 0.f; }
#pragma unroll
            for (int kk = 0; kk < 4; kk++) {
                mma16816(S[g][0], A[g][kk], kb[cur][kk]);
                mma16816(S[g][1], A[g][kk], kb[cur][kk] + 2);
            }
        }
        if (s < 15) {
#pragma unroll
            for (int kk = 0; kk < 4; kk++)
                ldsm4(kb[nxt][kk], kbaseL + (uint32_t)(((kb0 + 16) * 72 + kk * 16) * 2));
        }
        float2 bb0 = *(float2*)&B2[kb0 + c0];
        float2 bb1 = *(float2*)&B2[kb0 + 8 + c0];
#pragma unroll
        for (int g = 0; g < 2; g++) {
            float p0a = ex2(fmaf(S[g][0][0], SCL2, bb0.x));
            float p1a = ex2(fmaf(S[g][0][1], SCL2, bb0.y));
            float p2a = ex2(fmaf(S[g][0][2], SCL2, bb0.x));
            float p3a = ex2(fmaf(S[g][0][3], SCL2, bb0.y));
            float p0b = ex2(fmaf(S[g][1][0], SCL2, bb1.x));
            float p1b = ex2(fmaf(S[g][1][1], SCL2, bb1.y));
            float p2b = ex2(fmaf(S[g][1][2], SCL2, bb1.x));
            float p3b = ex2(fmaf(S[g][1][3], SCL2, bb1.y));
            l0[g] += p0a + p1a + p0b + p1b;
            l1[g] += p2a + p3a + p2b + p3b;
            pa[g][0] = packbf(p0a, p1a);
            pa[g][1] = packbf(p2a, p3a);
            pa[g][2] = packbf(p0b, p1b);
            pa[g][3] = packbf(p2b, p3b);
        }
#pragma unroll
        for (int nn = 0; nn < 4; nn++) {
            uint32_t vb[4];
            ldsm4t(vb, vbaseL + (uint32_t)((kb0 * 72 + nn * 16) * 2));
#pragma unroll
            for (int g = 0; g < 2; g++) {
                mma16816(O[g][2 * nn],     pa[g], vb);
                mma16816(O[g][2 * nn + 1], pa[g], vb + 2);
            }
        }
    }
#pragma unroll
    for (int g = 0; g < 2; g++) {
        float a = l0[g], c = l1[g];
        a += __shfl_xor_sync(~0u, a, 1);
        a += __shfl_xor_sync(~0u, a, 2);
        c += __shfl_xor_sync(~0u, c, 1);
        c += __shfl_xor_sync(~0u, c, 2);
        float inv0 = 1.f / a, inv1 = 1.f / c;
        bf16* o0 = g_o + ((size_t)(b * 4096 + s0 + w * 32 + g * 16 + rq)) * 256 + h * 64 + c0;
        bf16* o1 = o0 + 8 * 256;
#pragma unroll
        for (int t = 0; t < 8; t++) {
            *(uint32_t*)(o0 + t * 8) = packbf(O[g][t][0] * inv0, O[g][t][1] * inv0);
            *(uint32_t*)(o1 + t * 8) = packbf(O[g][t][2] * inv1, O[g][t][3] * inv1);
        }
    }
}

// ---- O projection + AdaLN + residual + float4 transposed epilogue -----------
// smem: As 33792 (stage [256][68]f 69632 overlays) | Md@69632 | Bo@72704 = 73728
__global__ void __launch_bounds__(256, 2)
oproj_kernel(const float* img, const float* bo, float* out) {
    extern __shared__ char smem[];
    bf16*  As = (bf16*)smem;
    float* Md = (float*)(smem + 69632);
    float* Bo = (float*)(smem + 72704);
    float* stage = (float*)smem;

    int tid = threadIdx.x, blk = blockIdx.x;
    int b = blk >> 6, s0 = (blk & 63) << 6;
    int w = tid >> 5, lane = tid & 31;

    Md[tid]       = g_mod[b * 768 + tid];
    Md[tid + 256] = g_mod[b * 768 + tid + 256];
    Md[tid + 512] = g_mod[b * 768 + tid + 512];
    Bo[tid] = bo[tid];
    {
        const uint4* src = (const uint4*)(g_o + (size_t)blk * 64 * 256);
        for (int u = tid; u < 2048; u += 256) {
            int row = u >> 5, j = u & 31;
            *((uint4*)(As + row * 264) + j) = src[row * 32 + j];
        }
    }
    __syncthreads();

    float acc[2][8][4];
#pragma unroll
    for (int m = 0; m < 2; m++)
#pragma unroll
        for (int n = 0; n < 8; n++)
#pragma unroll
            for (int q = 0; q < 4; q++) acc[m][n][q] = 0.f;

    mma_gemm64(smem_u32(As), (const uint4*)(g_wfrag + 3 * 65536), tid, acc);
    __syncthreads();                          // As dead; stage overlays it

    {
        int wm = w >> 2, wn = w & 3;
        int r0 = wm * 32 + (lane >> 2);
        int cb0 = wn * 64 + 2 * (lane & 3);
#pragma unroll
        for (int m = 0; m < 2; m++) {
            int row = r0 + m * 16;
#pragma unroll
            for (int n = 0; n < 8; n++) {
                int cb = cb0 + (n >> 1) * 16 + (n & 1) * 8;
                stage[cb * 68 + row]           = acc[m][n][0];
                stage[(cb + 1) * 68 + row]     = acc[m][n][1];
                stage[cb * 68 + row + 8]       = acc[m][n][2];
                stage[(cb + 1) * 68 + row + 8] = acc[m][n][3];
            }
        }
        __syncthreads();
    }

#pragma unroll
    for (int it = 0; it < 16; it++) {
        int c = w * 32 + it * 2 + (lane >> 4);
        int r4 = (lane & 15) * 4;
        float4 v = *(float4*)&stage[c * 68 + r4];
        float shift = Md[c], scv1 = 1.f + Md[c + 256], gate = Md[c + 512];
        float bias = Bo[c];
        const float4* xb = (const float4*)(img + ((size_t)(b * 256 + c)) * 4096 + s0 + r4);
        float4*       ob = (float4*)(out + ((size_t)(b * 256 + c)) * 4096 + s0 + r4);
        float4 x = *xb;
        float4 o;
        o.x = fmaf(gate, fmaf(v.x + bias, scv1, shift), x.x);
        o.y = fmaf(gate, fmaf(v.y + bias, scv1, shift), x.y);
        o.z = fmaf(gate, fmaf(v.z + bias, scv1, shift), x.z);
        o.w = fmaf(gate, fmaf(v.w + bias, scv1, shift), x.w);
        *ob = o;
    }
}

// ---------------- launcher ---------------------------------------------------
extern "C" void kernel_launch(void* const* d_in, const int* in_sizes, int n_in,
                              void* d_out, int out_size) {
    const float* img        = (const float*)d_in[0];
    const float* refs       = (const float*)d_in[1];
    const void*  masks      = d_in[2];
    const float* ref_embeds = (const float*)d_in[3];
    const float* ln_img_w   = (const float*)d_in[4];
    const float* ln_img_b   = (const float*)d_in[5];
    const float* ln_txt_w   = (const float*)d_in[6];
    const float* ln_txt_b   = (const float*)d_in[7];
    const float* Wq         = (const float*)d_in[8];
    const float* bq         = (const float*)d_in[9];
    const float* Wk         = (const float*)d_in[10];
    const float* bk         = (const float*)d_in[11];
    const float* Wv         = (const float*)d_in[12];
    const float* bv         = (const float*)d_in[13];
    const float* Wo         = (const float*)d_in[14];
    const float* bo         = (const float*)d_in[15];
    const float* Wada       = (const float*)d_in[16];
    const float* bada       = (const float*)d_in[17];
    float* out = (float*)d_out;

    cudaFuncSetAttribute(qkvproj_kernel, cudaFuncAttributeMaxDynamicSharedMemorySize, 70272);
    cudaFuncSetAttribute(attn_kernel,    cudaFuncAttributeMaxDynamicSharedMemorySize, 74752);
    cudaFuncSetAttribute(oproj_kernel,   cudaFuncAttributeMaxDynamicSharedMemorySize, 73728);

    prep_kernel<<<1585, 256>>>(masks, Wq, Wk, Wv, Wo, refs, ln_txt_w, ln_txt_b,
                               ref_embeds, Wada, bada);
    qkvproj_kernel<<<1152, 256, 70272>>>(img, ln_img_w, ln_img_b, bq, bk, bv);
    attn_kernel<<<dim3(16, 4, 16), 256, 74752>>>();
    oproj_kernel<<<1024, 256, 73728>>>(img, bo, out);    // 4th launch: profiled
}

// round 14
// speedup vs baseline: 1.1837x; 1.1837x over previous
#include <cuda_runtime.h>
#include <cuda_bf16.h>
#include <cstdint>

typedef __nv_bfloat16 bf16;

#define Bc   16
#define Cc   256
#define Sc   4096
#define Lc   256
#define Ec   256

// ---------------- scratch (device globals; no allocation allowed) -----------
__device__ bf16  g_q [Bc * Sc * Ec];       // Q projection, bf16
__device__ bf16  g_k [Bc * Lc * Ec];       // K projection, bf16
__device__ bf16  g_v [Bc * Lc * Ec];       // V projection, bf16
__device__ bf16  g_o [Bc * Sc * Ec];       // attention output, bf16
__device__ bf16  g_kn[Bc * Lc * Cc];       // LN(refs), bf16
__device__ bf16  g_wq[Cc * Ec];
__device__ bf16  g_wk[Cc * Ec];
__device__ bf16  g_wv[Cc * Ec];
__device__ bf16  g_wo[Ec * Cc];
__device__ float g_mod[Bc * 3 * Cc];       // shift|scale|gate per batch
__device__ float g_kbias[Bc * Lc];         // 0 or -1e30

// ---------------- small asm helpers ------------------------------------------
__device__ __forceinline__ uint32_t smem_u32(const void* p) {
    uint32_t a;
    asm("{ .reg .u64 t; cvta.to.shared.u64 t, %1; cvt.u32.u64 %0, t; }" : "=r"(a) : "l"(p));
    return a;
}
__device__ __forceinline__ float ex2(float x) {
    float y; asm("ex2.approx.ftz.f32 %0, %1;" : "=f"(y) : "f"(x)); return y;
}
__device__ __forceinline__ uint32_t packbf(float lo, float hi) {
    uint32_t d; asm("cvt.rn.bf16x2.f32 %0, %1, %2;" : "=r"(d) : "f"(hi), "f"(lo)); return d;
}
__device__ __forceinline__ void ldsm4(uint32_t* r, uint32_t a) {
    asm volatile("ldmatrix.sync.aligned.m8n8.x4.shared.b16 {%0,%1,%2,%3}, [%4];"
                 : "=r"(r[0]), "=r"(r[1]), "=r"(r[2]), "=r"(r[3]) : "r"(a));
}
__device__ __forceinline__ void ldsm4t(uint32_t* r, uint32_t a) {
    asm volatile("ldmatrix.sync.aligned.m8n8.x4.trans.shared.b16 {%0,%1,%2,%3}, [%4];"
                 : "=r"(r[0]), "=r"(r[1]), "=r"(r[2]), "=r"(r[3]) : "r"(a));
}
__device__ __forceinline__ void mma16816(float* d, const uint32_t* a, const uint32_t* b) {
    asm volatile("mma.sync.aligned.m16n8k16.row.col.f32.bf16.bf16.f32 "
                 "{%0,%1,%2,%3},{%4,%5,%6,%7},{%8,%9},{%0,%1,%2,%3};"
                 : "+f"(d[0]), "+f"(d[1]), "+f"(d[2]), "+f"(d[3])
                 : "r"(a[0]), "r"(a[1]), "r"(a[2]), "r"(a[3]), "r"(b[0]), "r"(b[1]));
}
__device__ __forceinline__ void cp16(uint32_t saddr, const void* gaddr) {
    asm volatile("cp.async.cg.shared.global [%0], [%1], 16;" :: "r"(saddr), "l"(gaddr));
}
#define CP_COMMIT() asm volatile("cp.async.commit_group;" ::: "memory")
#define CP_WAIT(n)  asm volatile("cp.async.wait_group %0;" :: "n"(n) : "memory")

// ============ fused prep: mask | wconv | lnref | mod in one launch ===========
__global__ void prep_kernel(const void* masks,
                            const float* wq, const float* wk,
                            const float* wv, const float* wo,
                            const float* refs, const float* lw_t, const float* lb_t,
                            const float* re, const float* Wada, const float* bada) {
    __shared__ char shbuf[33312];
    int blk = blockIdx.x, tid = threadIdx.x;

    if (blk == 0) {
        int* flags = (int*)shbuf;
        if (tid == 0) { flags[0] = 0; flags[1] = 0; flags[2] = 0; }
        __syncthreads();
        const unsigned char* mb = (const unsigned char*)masks;
        const float*         mf = (const float*)masks;
        const int*           mi = (const int*)masks;
        for (int i = tid; i < 1024; i += 256) {
            float f = mf[i];
            if (!(f == 0.f || f == 1.f)) flags[0] = 1;
            if (f == 1.f) flags[1] = 1;
        }
        for (int i = tid; i < Bc * Lc; i += 256)
            if ((i & 3) && mb[i]) flags[2] = 1;
        __syncthreads();
        bool isf = (!flags[0]) && flags[1];
        bool isu8 = flags[2];
        for (int i = tid; i < Bc * Lc; i += 256) {
            int m;
            if (isf)       m = (mf[i] != 0.f);
            else if (isu8) m = mb[i];
            else           m = mi[i];
            g_kbias[i] = m ? -1e30f : 0.f;
        }
    } else if (blk <= 256) {
        int i = (blk - 1) * 256 + tid;
        g_wq[i] = __float2bfloat16(wq[i]);
        g_wk[i] = __float2bfloat16(wk[i]);
        g_wv[i] = __float2bfloat16(wv[i]);
        g_wo[i] = __float2bfloat16(wo[i]);
    } else if (blk <= 768) {
        int lane = tid & 31, w = tid >> 5;
        int row = (blk - 257) * 8 + w;
        const float* rr = refs + (size_t)row * 256;
        float v[8], s = 0.f, s2 = 0.f;
#pragma unroll
        for (int i = 0; i < 8; i++) {
            v[i] = rr[lane + 32 * i];
            s += v[i]; s2 += v[i] * v[i];
        }
#pragma unroll
        for (int o = 16; o; o >>= 1) {
            s  += __shfl_xor_sync(~0u, s,  o);
            s2 += __shfl_xor_sync(~0u, s2, o);
        }
        float mu = s * (1.f / 256.f);
        float rs = rsqrtf(s2 * (1.f / 256.f) - mu * mu + 1e-5f);
#pragma unroll
        for (int i = 0; i < 8; i++) {
            int c = lane + 32 * i;
            g_kn[(size_t)row * 256 + c] = __float2bfloat16((v[i] - mu) * rs * lw_t[c] + lb_t[c]);
        }
    } else {
        float* sv = (float*)shbuf;                 // [16][264]
        float* wt = (float*)(shbuf + 16896);       // [256][16]
        int c0 = (blk - 769) * 16;
        for (int u = tid; u < 4096; u += 256) {
            float x = re[u];
            sv[(u >> 8) * 264 + (u & 255)] = x / (1.f + __expf(-x));
        }
        for (int u = tid; u < 4096; u += 256) {
            int k = u >> 4, c = u & 15;
            wt[k * 16 + c] = Wada[(size_t)k * 768 + c0 + c];
        }
        __syncthreads();
        int b = tid >> 4, c = tid & 15;
        const float* svb = sv + b * 264;
        float acc = bada[c0 + c];
#pragma unroll 8
        for (int k = 0; k < 256; k++) acc = fmaf(svb[k], wt[k * 16 + c], acc);
        g_mod[b * 768 + c0 + c] = acc;
    }
}

// ============ raw-mma GEMM core: 64x256x256 per block, 2 CTA/SM ==============
// generic 64-row x 512B-row async copy into stride-528 smem tile
__device__ __forceinline__ void issue_tile64(void* dstSmem, const void* src, int tid) {
    uint32_t dstb = smem_u32(dstSmem);
    const char* s = (const char*)src;
#pragma unroll
    for (int v = tid; v < 2048; v += 256) {
        int r = v >> 5, c8 = v & 31;
        cp16(dstb + r * 528 + c8 * 16, s + r * 512 + c8 * 16);
    }
}
__device__ __forceinline__ void issue_wchunk(bf16* WsBuf, const bf16* Wg, int kk, int tid) {
    issue_tile64(WsBuf, Wg + (size_t)kk * 64 * 256, tid);
}

__device__ __forceinline__ void mma_gemm64(uint32_t sA, bf16* Ws0, bf16* Ws1,
                                           const bf16* Wg, int tid,
                                           float acc[2][8][4]) {
    int w = tid >> 5, lane = tid & 31;
    int wm = w >> 2, wn = w & 3;
    uint32_t aBase = sA + (uint32_t)(((wm * 32 + (lane & 15)) * 264 + (lane >> 4) * 8) * 2);
    int krow = ((lane >> 3) & 1) * 8 + (lane & 7);
    int ncol = ((lane >> 4) & 1) * 8;
    bf16* bufs[2] = {Ws0, Ws1};
#pragma unroll
    for (int kk = 0; kk < 4; kk++) {
        if (kk < 3) { issue_wchunk(bufs[kk & 1], Wg, kk + 1, tid); CP_COMMIT(); CP_WAIT(1); }
        else        { CP_WAIT(0); }
        __syncthreads();
        uint32_t sB = smem_u32(bufs[(kk + 1) & 1]) +
                      (uint32_t)((krow * 264 + wn * 64 + ncol) * 2);
#pragma unroll
        for (int k16 = 0; k16 < 4; k16++) {
            uint32_t Af[2][4];
#pragma unroll
            for (int m = 0; m < 2; m++)
                ldsm4(Af[m], aBase + (uint32_t)((m * 16 * 264 + kk * 64 + k16 * 16) * 2));
#pragma unroll
            for (int n2 = 0; n2 < 4; n2++) {
                uint32_t Bf[4];
                ldsm4t(Bf, sB + (uint32_t)((k16 * 16 * 264 + n2 * 16) * 2));
#pragma unroll
                for (int m = 0; m < 2; m++) {
                    mma16816(acc[m][2 * n2],     Af[m], Bf);
                    mma16816(acc[m][2 * n2 + 1], Af[m], Bf + 2);
                }
            }
        }
        __syncthreads();
    }
}

// direct-from-register bf16 epilogue: acc + bias -> dst[row][256]
__device__ __forceinline__ void epilogue_bf16(float acc[2][8][4], const float* sB,
                                              bf16* dst, int tid) {
    int w = tid >> 5, lane = tid & 31;
    int wm = w >> 2, wn = w & 3;
    int r0 = wm * 32 + (lane >> 2);
    int cb0 = wn * 64 + 2 * (lane & 3);
#pragma unroll
    for (int m = 0; m < 2; m++) {
        int row = r0 + m * 16;
#pragma unroll
        for (int n = 0; n < 8; n++) {
            int cb = cb0 + (n >> 1) * 16 + (n & 1) * 8;
            float bx = sB[cb], by = sB[cb + 1];
            *(uint32_t*)(dst + (size_t)row * 256 + cb) =
                packbf(acc[m][n][0] + bx, acc[m][n][1] + by);
            *(uint32_t*)(dst + (size_t)(row + 8) * 256 + cb) =
                packbf(acc[m][n][2] + bx, acc[m][n][3] + by);
        }
    }
}

// ---- merged Q + K/V projection ----------------------------------------------
// blk < 1024: Q path (transpose+LN+GEMM). blk >= 1024: K/V path (async A load).
__global__ void __launch_bounds__(256, 2)
qkvproj_kernel(const float* img, const float* lnw, const float* lnb,
               const float* bq, const float* bk, const float* bv) {
    extern __shared__ char smem[];
    bf16*  As  = (bf16*)smem;
    bf16*  Ws0 = (bf16*)(smem + 33792);
    bf16*  Ws1 = (bf16*)(smem + 67584);
    float* lw  = (float*)(smem + 101376);
    float* lb  = (float*)(smem + 102400);
    float* sB  = (float*)(smem + 103424);
    float* Xf  = (float*)(smem + 33792);       // overlays Ws0 (Q path LN stage)

    int tid = threadIdx.x, blk = blockIdx.x;
    int w = tid >> 5, lane = tid & 31;

    if (blk < 1024) {
        int b = blk >> 6, s0 = (blk & 63) << 6;
        issue_wchunk(Ws1, g_wq, 0, tid); CP_COMMIT();
        lw[tid] = lnw[tid]; lb[tid] = lnb[tid]; sB[tid] = bq[tid];

        for (int g = 0; g < 2; g++) {
            for (int i = 0; i < 32; i++) {
                int c = w + 8 * i;
                Xf[lane * 261 + c] = img[((size_t)(b * 256 + c)) * 4096 + s0 + g * 32 + lane];
            }
            __syncthreads();
            for (int j = 0; j < 4; j++) {
                int rl = w * 4 + j;
                float v[8], s = 0.f, s2 = 0.f;
#pragma unroll
                for (int i = 0; i < 8; i++) {
                    v[i] = Xf[rl * 261 + lane + 32 * i];
                    s += v[i]; s2 += v[i] * v[i];
                }
#pragma unroll
                for (int o = 16; o; o >>= 1) {
                    s  += __shfl_xor_sync(~0u, s,  o);
                    s2 += __shfl_xor_sync(~0u, s2, o);
                }
                float mu = s * (1.f / 256.f);
                float rs = rsqrtf(s2 * (1.f / 256.f) - mu * mu + 1e-5f);
                int R = g * 32 + rl;
#pragma unroll
                for (int i = 0; i < 8; i++) {
                    int c = lane + 32 * i;
                    As[R * 264 + c] = __float2bfloat16((v[i] - mu) * rs * lw[c] + lb[c]);
                }
            }
            __syncthreads();
        }

        float acc[2][8][4];
#pragma unroll
        for (int m = 0; m < 2; m++)
#pragma unroll
            for (int n = 0; n < 8; n++)
#pragma unroll
                for (int q = 0; q < 4; q++) acc[m][n][q] = 0.f;
        mma_gemm64(smem_u32(As), Ws0, Ws1, g_wq, tid, acc);
        epilogue_bf16(acc, sB, g_q + (size_t)blk * 64 * 256, tid);
    } else {
        int blk2 = blk - 1024;
        int which = blk2 >> 6, chunk = blk2 & 63;
        const bf16* Wg = which ? g_wv : g_wk;
        // weight chunk 0 + A tile in ONE cp.async group; drains at gemm's WAIT(1)
        issue_wchunk(Ws1, Wg, 0, tid);
        issue_tile64(As, g_kn + (size_t)chunk * 64 * 256, tid);
        CP_COMMIT();
        sB[tid] = which ? bv[tid] : bk[tid];

        float acc[2][8][4];
#pragma unroll
        for (int m = 0; m < 2; m++)
#pragma unroll
            for (int n = 0; n < 8; n++)
#pragma unroll
                for (int q = 0; q < 4; q++) acc[m][n][q] = 0.f;
        mma_gemm64(smem_u32(As), Ws0, Ws1, Wg, tid, acc);
        epilogue_bf16(acc, sB, (which ? g_v : g_k) + (size_t)chunk * 64 * 256, tid);
    }
}

// ------- flash attention: 256 q/block, 32-row warp tiles, K double-buffer ----
// smem: Ks[256][72] 36864 | Vs[256][72] 36864@36864 | B2[256] 1024@73728 = 74752
__global__ void __launch_bounds__(256, 1) attn_kernel() {
    extern __shared__ char smem[];
    bf16*  Ks = (bf16*)smem;
    bf16*  Vs = (bf16*)(smem + 36864);
    float* B2 = (float*)(smem + 73728);

    int tid = threadIdx.x, w = tid >> 5, lane = tid & 31;
    int s0 = blockIdx.x * 256, h = blockIdx.y, b = blockIdx.z;

    const bf16* ksrc = g_k + ((size_t)(b * 256)) * 256 + h * 64;
    const bf16* vsrc = g_v + ((size_t)(b * 256)) * 256 + h * 64;
    for (int u = tid; u < 2048; u += 256) {
        int r = u >> 3, j = u & 7;
        *(uint4*)(Ks + r * 72 + j * 8) = *(const uint4*)(ksrc + (size_t)r * 256 + j * 8);
        *(uint4*)(Vs + r * 72 + j * 8) = *(const uint4*)(vsrc + (size_t)r * 256 + j * 8);
    }
    B2[tid] = g_kbias[b * 256 + tid] * 1.44269504f;

    int rq = lane >> 2, c0 = 2 * (lane & 3);
    uint32_t A[2][4][4];
#pragma unroll
    for (int g = 0; g < 2; g++) {
        const bf16* q0 = g_q + ((size_t)(b * 4096 + s0 + w * 32 + g * 16 + rq)) * 256 + h * 64;
        const bf16* q1 = q0 + 8 * 256;
#pragma unroll
        for (int kk = 0; kk < 4; kk++) {
            A[g][kk][0] = *(const uint32_t*)(q0 + kk * 16 + c0);
            A[g][kk][1] = *(const uint32_t*)(q1 + kk * 16 + c0);
            A[g][kk][2] = *(const uint32_t*)(q0 + kk * 16 + c0 + 8);
            A[g][kk][3] = *(const uint32_t*)(q1 + kk * 16 + c0 + 8);
        }
    }
    __syncthreads();

    uint32_t sbK = smem_u32(Ks), sbV = smem_u32(Vs);
    int nrow_off = ((lane >> 4) & 1) * 8 + (lane & 7);
    int koff     = ((lane >> 3) & 1) * 8;
    uint32_t kbaseL = sbK + (uint32_t)(nrow_off * 72 + koff) * 2;
    int krow_off = ((lane >> 3) & 1) * 8 + (lane & 7);
    int ncol_off = ((lane >> 4) & 1) * 8;
    uint32_t vbaseL = sbV + (uint32_t)(krow_off * 72 + ncol_off) * 2;

    const float SCL2 = 0.125f * 1.44269504f;
    float O[2][8][4];
#pragma unroll
    for (int g = 0; g < 2; g++)
#pragma unroll
        for (int t = 0; t < 8; t++)
#pragma unroll
            for (int q = 0; q < 4; q++) O[g][t][q] = 0.f;
    float l0[2] = {0.f, 0.f}, l1[2] = {0.f, 0.f};

    uint32_t kb[2][4][4];
#pragma unroll
    for (int kk = 0; kk < 4; kk++)
        ldsm4(kb[0][kk], kbaseL + (uint32_t)((kk * 16) * 2));

    uint32_t pa[2][4];
#pragma unroll
    for (int s = 0; s < 16; s++) {
        int cur = s & 1, nxt = cur ^ 1;
        int kb0 = s * 16;
        float S[2][2][4];
#pragma unroll
        for (int g = 0; g < 2; g++) {
#pragma unroll
            for (int q = 0; q < 4; q++) { S[g][0][q] = 0.f; S[g][1][q] = 0.f; }
#pragma unroll
            for (int kk = 0; kk < 4; kk++) {
                mma16816(S[g][0], A[g][kk], kb[cur][kk]);
                mma16816(S[g][1], A[g][kk], kb[cur][kk] + 2);
            }
        }
        if (s < 15) {
#pragma unroll
            for (int kk = 0; kk < 4; kk++)
                ldsm4(kb[nxt][kk], kbaseL + (uint32_t)(((kb0 + 16) * 72 + kk * 16) * 2));
        }
        float2 bb0 = *(float2*)&B2[kb0 + c0];
        float2 bb1 = *(float2*)&B2[kb0 + 8 + c0];
#pragma unroll
        for (int g = 0; g < 2; g++) {
            float p0a = ex2(fmaf(S[g][0][0], SCL2, bb0.x));
            float p1a = ex2(fmaf(S[g][0][1], SCL2, bb0.y));
            float p2a = ex2(fmaf(S[g][0][2], SCL2, bb0.x));
            float p3a = ex2(fmaf(S[g][0][3], SCL2, bb0.y));
            float p0b = ex2(fmaf(S[g][1][0], SCL2, bb1.x));
            float p1b = ex2(fmaf(S[g][1][1], SCL2, bb1.y));
            float p2b = ex2(fmaf(S[g][1][2], SCL2, bb1.x));
            float p3b = ex2(fmaf(S[g][1][3], SCL2, bb1.y));
            l0[g] += p0a + p1a + p0b + p1b;
            l1[g] += p2a + p3a + p2b + p3b;
            pa[g][0] = packbf(p0a, p1a);
            pa[g][1] = packbf(p2a, p3a);
            pa[g][2] = packbf(p0b, p1b);
            pa[g][3] = packbf(p2b, p3b);
        }
#pragma unroll
        for (int nn = 0; nn < 4; nn++) {
            uint32_t vb[4];
            ldsm4t(vb, vbaseL + (uint32_t)((kb0 * 72 + nn * 16) * 2));
#pragma unroll
            for (int g = 0; g < 2; g++) {
                mma16816(O[g][2 * nn],     pa[g], vb);
                mma16816(O[g][2 * nn + 1], pa[g], vb + 2);
            }
        }
    }
#pragma unroll
    for (int g = 0; g < 2; g++) {
        float a = l0[g], c = l1[g];
        a += __shfl_xor_sync(~0u, a, 1);
        a += __shfl_xor_sync(~0u, a, 2);
        c += __shfl_xor_sync(~0u, c, 1);
        c += __shfl_xor_sync(~0u, c, 2);
        float inv0 = 1.f / a, inv1 = 1.f / c;
        bf16* o0 = g_o + ((size_t)(b * 4096 + s0 + w * 32 + g * 16 + rq)) * 256 + h * 64 + c0;
        bf16* o1 = o0 + 8 * 256;
#pragma unroll
        for (int t = 0; t < 8; t++) {
            *(uint32_t*)(o0 + t * 8) = packbf(O[g][t][0] * inv0, O[g][t][1] * inv0);
            *(uint32_t*)(o1 + t * 8) = packbf(O[g][t][2] * inv1, O[g][t][3] * inv1);
        }
    }
}

// ---- O projection + AdaLN + residual + float4 transposed epilogue -----------
__global__ void __launch_bounds__(256, 2)
oproj_kernel(const float* img, const float* bo, float* out) {
    extern __shared__ char smem[];
    bf16*  As  = (bf16*)smem;
    bf16*  Ws0 = (bf16*)(smem + 33792);
    bf16*  Ws1 = (bf16*)(smem + 67584);
    float* Md  = (float*)(smem + 101376);
    float* Bo  = (float*)(smem + 104448);
    float* stage = (float*)smem;             // [256 cols][68] post-GEMM

    int tid = threadIdx.x, blk = blockIdx.x;
    int b = blk >> 6, s0 = (blk & 63) << 6;
    int w = tid >> 5, lane = tid & 31;

    // weight chunk 0 + A tile (g_o, already bf16) in one cp.async group
    issue_wchunk(Ws1, g_wo, 0, tid);
    issue_tile64(As, g_o + (size_t)blk * 64 * 256, tid);
    CP_COMMIT();

    Md[tid]       = g_mod[b * 768 + tid];
    Md[tid + 256] = g_mod[b * 768 + tid + 256];
    Md[tid + 512] = g_mod[b * 768 + tid + 512];
    Bo[tid] = bo[tid];

    float acc[2][8][4];
#pragma unroll
    for (int m = 0; m < 2; m++)
#pragma unroll
        for (int n = 0; n < 8; n++)
#pragma unroll
            for (int q = 0; q < 4; q++) acc[m][n][q] = 0.f;

    mma_gemm64(smem_u32(As), Ws0, Ws1, g_wo, tid, acc);

    // stage col-major [c][r] directly from acc registers (As dead now)
    {
        int wm = w >> 2, wn = w & 3;
        int r0 = wm * 32 + (lane >> 2);
        int cb0 = wn * 64 + 2 * (lane & 3);
#pragma unroll
        for (int m = 0; m < 2; m++) {
            int row = r0 + m * 16;
#pragma unroll
            for (int n = 0; n < 8; n++) {
                int cb = cb0 + (n >> 1) * 16 + (n & 1) * 8;
                stage[cb * 68 + row]           = acc[m][n][0];
                stage[(cb + 1) * 68 + row]     = acc[m][n][1];
                stage[cb * 68 + row + 8]       = acc[m][n][2];
                stage[(cb + 1) * 68 + row + 8] = acc[m][n][3];
            }
        }
        __syncthreads();
    }

    // float4 vectorized modulate + residual + transposed write
#pragma unroll
    for (int it = 0; it < 16; it++) {
        int c = w * 32 + it * 2 + (lane >> 4);
        int r4 = (lane & 15) * 4;
        float4 v = *(float4*)&stage[c * 68 + r4];
        float shift = Md[c], scv1 = 1.f + Md[c + 256], gate = Md[c + 512];
        float bias = Bo[c];
        const float4* xb = (const float4*)(img + ((size_t)(b * 256 + c)) * 4096 + s0 + r4);
        float4*       ob = (float4*)(out + ((size_t)(b * 256 + c)) * 4096 + s0 + r4);
        float4 x = *xb;
        float4 o;
        o.x = fmaf(gate, fmaf(v.x + bias, scv1, shift), x.x);
        o.y = fmaf(gate, fmaf(v.y + bias, scv1, shift), x.y);
        o.z = fmaf(gate, fmaf(v.z + bias, scv1, shift), x.z);
        o.w = fmaf(gate, fmaf(v.w + bias, scv1, shift), x.w);
        *ob = o;
    }
}

// ---------------- launcher ---------------------------------------------------
extern "C" void kernel_launch(void* const* d_in, const int* in_sizes, int n_in,
                              void* d_out, int out_size) {
    const float* img        = (const float*)d_in[0];
    const float* refs       = (const float*)d_in[1];
    const void*  masks      = d_in[2];
    const float* ref_embeds = (const float*)d_in[3];
    const float* ln_img_w   = (const float*)d_in[4];
    const float* ln_img_b   = (const float*)d_in[5];
    const float* ln_txt_w   = (const float*)d_in[6];
    const float* ln_txt_b   = (const float*)d_in[7];
    const float* Wq         = (const float*)d_in[8];
    const float* bq         = (const float*)d_in[9];
    const float* Wk         = (const float*)d_in[10];
    const float* bk         = (const float*)d_in[11];
    const float* Wv         = (const float*)d_in[12];
    const float* bv         = (const float*)d_in[13];
    const float* Wo         = (const float*)d_in[14];
    const float* bo         = (const float*)d_in[15];
    const float* Wada       = (const float*)d_in[16];
    const float* bada       = (const float*)d_in[17];
    float* out = (float*)d_out;

    cudaFuncSetAttribute(qkvproj_kernel, cudaFuncAttributeMaxDynamicSharedMemorySize, 104448);
    cudaFuncSetAttribute(attn_kernel,    cudaFuncAttributeMaxDynamicSharedMemorySize, 74752);
    cudaFuncSetAttribute(oproj_kernel,   cudaFuncAttributeMaxDynamicSharedMemorySize, 105472);

    prep_kernel<<<817, 256>>>(masks, Wq, Wk, Wv, Wo, refs, ln_txt_w, ln_txt_b,
                              ref_embeds, Wada, bada);
    qkvproj_kernel<<<1152, 256, 104448>>>(img, ln_img_w, ln_img_b, bq, bk, bv);
    attn_kernel<<<dim3(16, 4, 16), 256, 74752>>>();
    oproj_kernel<<<1024, 256, 105472>>>(img, bo, out);
}

// round 15
// speedup vs baseline: 1.3219x; 1.1167x over previous
#include <cuda_runtime.h>
#include <cuda_bf16.h>
#include <cstdint>

typedef __nv_bfloat16 bf16;

#define Bc   16
#define Cc   256
#define Sc   4096
#define Lc   256
#define Ec   256

// ---------------- scratch (device globals; no allocation allowed) -----------
__device__ bf16  g_q [Bc * Sc * Ec];       // Q projection, bf16
__device__ bf16  g_k [Bc * Lc * Ec];       // K projection, bf16
__device__ bf16  g_v [Bc * Lc * Ec];       // V projection, bf16
__device__ bf16  g_o [Bc * Sc * Ec];       // attention output, bf16
__device__ bf16  g_kn[Bc * Lc * Cc];       // LN(refs), bf16
__device__ bf16  g_wq[Cc * Ec];
__device__ bf16  g_wk[Cc * Ec];
__device__ bf16  g_wv[Cc * Ec];
__device__ bf16  g_wo[Ec * Cc];
__device__ float g_mod[Bc * 3 * Cc];       // shift|scale|gate per batch
__device__ float g_kbias[Bc * Lc];         // 0 or -1e30

// ---------------- small asm helpers ------------------------------------------
__device__ __forceinline__ uint32_t smem_u32(const void* p) {
    uint32_t a;
    asm("{ .reg .u64 t; cvta.to.shared.u64 t, %1; cvt.u32.u64 %0, t; }" : "=r"(a) : "l"(p));
    return a;
}
__device__ __forceinline__ float ex2(float x) {
    float y; asm("ex2.approx.ftz.f32 %0, %1;" : "=f"(y) : "f"(x)); return y;
}
__device__ __forceinline__ uint32_t packbf(float lo, float hi) {
    uint32_t d; asm("cvt.rn.bf16x2.f32 %0, %1, %2;" : "=r"(d) : "f"(hi), "f"(lo)); return d;
}
__device__ __forceinline__ void ldsm4(uint32_t* r, uint32_t a) {
    asm volatile("ldmatrix.sync.aligned.m8n8.x4.shared.b16 {%0,%1,%2,%3}, [%4];"
                 : "=r"(r[0]), "=r"(r[1]), "=r"(r[2]), "=r"(r[3]) : "r"(a));
}
__device__ __forceinline__ void ldsm4t(uint32_t* r, uint32_t a) {
    asm volatile("ldmatrix.sync.aligned.m8n8.x4.trans.shared.b16 {%0,%1,%2,%3}, [%4];"
                 : "=r"(r[0]), "=r"(r[1]), "=r"(r[2]), "=r"(r[3]) : "r"(a));
}
__device__ __forceinline__ void mma16816(float* d, const uint32_t* a, const uint32_t* b) {
    asm volatile("mma.sync.aligned.m16n8k16.row.col.f32.bf16.bf16.f32 "
                 "{%0,%1,%2,%3},{%4,%5,%6,%7},{%8,%9},{%0,%1,%2,%3};"
                 : "+f"(d[0]), "+f"(d[1]), "+f"(d[2]), "+f"(d[3])
                 : "r"(a[0]), "r"(a[1]), "r"(a[2]), "r"(a[3]), "r"(b[0]), "r"(b[1]));
}
__device__ __forceinline__ void cp16(uint32_t saddr, const void* gaddr) {
    asm volatile("cp.async.cg.shared.global [%0], [%1], 16;" :: "r"(saddr), "l"(gaddr));
}
#define CP_COMMIT() asm volatile("cp.async.commit_group;" ::: "memory")
#define CP_WAIT(n)  asm volatile("cp.async.wait_group %0;" :: "n"(n) : "memory")

// ============ fused prep: mask | wconv | lnref | mod in one launch ===========
__global__ void prep_kernel(const void* masks,
                            const float* wq, const float* wk,
                            const float* wv, const float* wo,
                            const float* refs, const float* lw_t, const float* lb_t,
                            const float* re, const float* Wada, const float* bada) {
    __shared__ char shbuf[33312];
    int blk = blockIdx.x, tid = threadIdx.x;

    if (blk == 0) {
        int* flags = (int*)shbuf;
        if (tid == 0) { flags[0] = 0; flags[1] = 0; flags[2] = 0; }
        __syncthreads();
        const unsigned char* mb = (const unsigned char*)masks;
        const float*         mf = (const float*)masks;
        const int*           mi = (const int*)masks;
        for (int i = tid; i < 1024; i += 256) {
            float f = mf[i];
            if (!(f == 0.f || f == 1.f)) flags[0] = 1;
            if (f == 1.f) flags[1] = 1;
        }
        for (int i = tid; i < Bc * Lc; i += 256)
            if ((i & 3) && mb[i]) flags[2] = 1;
        __syncthreads();
        bool isf = (!flags[0]) && flags[1];
        bool isu8 = flags[2];
        for (int i = tid; i < Bc * Lc; i += 256) {
            int m;
            if (isf)       m = (mf[i] != 0.f);
            else if (isu8) m = mb[i];
            else           m = mi[i];
            g_kbias[i] = m ? -1e30f : 0.f;
        }
    } else if (blk <= 256) {
        int i = (blk - 1) * 256 + tid;
        g_wq[i] = __float2bfloat16(wq[i]);
        g_wk[i] = __float2bfloat16(wk[i]);
        g_wv[i] = __float2bfloat16(wv[i]);
        g_wo[i] = __float2bfloat16(wo[i]);
    } else if (blk <= 768) {
        int lane = tid & 31, w = tid >> 5;
        int row = (blk - 257) * 8 + w;
        const float* rr = refs + (size_t)row * 256;
        float v[8], s = 0.f, s2 = 0.f;
#pragma unroll
        for (int i = 0; i < 8; i++) {
            v[i] = rr[lane + 32 * i];
            s += v[i]; s2 += v[i] * v[i];
        }
#pragma unroll
        for (int o = 16; o; o >>= 1) {
            s  += __shfl_xor_sync(~0u, s,  o);
            s2 += __shfl_xor_sync(~0u, s2, o);
        }
        float mu = s * (1.f / 256.f);
        float rs = rsqrtf(s2 * (1.f / 256.f) - mu * mu + 1e-5f);
#pragma unroll
        for (int i = 0; i < 8; i++) {
            int c = lane + 32 * i;
            g_kn[(size_t)row * 256 + c] = __float2bfloat16((v[i] - mu) * rs * lw_t[c] + lb_t[c]);
        }
    } else {
        float* sv = (float*)shbuf;                 // [16][264]
        float* wt = (float*)(shbuf + 16896);       // [256][16]
        int c0 = (blk - 769) * 16;
        for (int u = tid; u < 4096; u += 256) {
            float x = re[u];
            sv[(u >> 8) * 264 + (u & 255)] = x / (1.f + __expf(-x));
        }
        for (int u = tid; u < 4096; u += 256) {
            int k = u >> 4, c = u & 15;
            wt[k * 16 + c] = Wada[(size_t)k * 768 + c0 + c];
        }
        __syncthreads();
        int b = tid >> 4, c = tid & 15;
        const float* svb = sv + b * 264;
        float acc = bada[c0 + c];
#pragma unroll 8
        for (int k = 0; k < 256; k++) acc = fmaf(svb[k], wt[k * 16 + c], acc);
        g_mod[b * 768 + c0 + c] = acc;
    }
}

// ============ raw-mma GEMM core: 64x256x256 per block, 2 CTA/SM ==============
__device__ __forceinline__ void issue_tile64(void* dstSmem, const void* src, int tid) {
    uint32_t dstb = smem_u32(dstSmem);
    const char* s = (const char*)src;
#pragma unroll
    for (int v = tid; v < 2048; v += 256) {
        int r = v >> 5, c8 = v & 31;
        cp16(dstb + r * 528 + c8 * 16, s + r * 512 + c8 * 16);
    }
}
__device__ __forceinline__ void issue_wchunk(bf16* WsBuf, const bf16* Wg, int kk, int tid) {
    issue_tile64(WsBuf, Wg + (size_t)kk * 64 * 256, tid);
}

__device__ __forceinline__ void mma_gemm64(uint32_t sA, bf16* Ws0, bf16* Ws1,
                                           const bf16* Wg, int tid,
                                           float acc[2][8][4]) {
    int w = tid >> 5, lane = tid & 31;
    int wm = w >> 2, wn = w & 3;
    uint32_t aBase = sA + (uint32_t)(((wm * 32 + (lane & 15)) * 264 + (lane >> 4) * 8) * 2);
    int krow = ((lane >> 3) & 1) * 8 + (lane & 7);
    int ncol = ((lane >> 4) & 1) * 8;
    bf16* bufs[2] = {Ws0, Ws1};
#pragma unroll
    for (int kk = 0; kk < 4; kk++) {
        if (kk < 3) { issue_wchunk(bufs[kk & 1], Wg, kk + 1, tid); CP_COMMIT(); CP_WAIT(1); }
        else        { CP_WAIT(0); }
        __syncthreads();
        uint32_t sB = smem_u32(bufs[(kk + 1) & 1]) +
                      (uint32_t)((krow * 264 + wn * 64 + ncol) * 2);
#pragma unroll
        for (int k16 = 0; k16 < 4; k16++) {
            uint32_t Af[2][4];
#pragma unroll
            for (int m = 0; m < 2; m++)
                ldsm4(Af[m], aBase + (uint32_t)((m * 16 * 264 + kk * 64 + k16 * 16) * 2));
#pragma unroll
            for (int n2 = 0; n2 < 4; n2++) {
                uint32_t Bf[4];
                ldsm4t(Bf, sB + (uint32_t)((k16 * 16 * 264 + n2 * 16) * 2));
#pragma unroll
                for (int m = 0; m < 2; m++) {
                    mma16816(acc[m][2 * n2],     Af[m], Bf);
                    mma16816(acc[m][2 * n2 + 1], Af[m], Bf + 2);
                }
            }
        }
        __syncthreads();
    }
}

// direct-from-register bf16 epilogue: acc + bias -> dst[row][256]
__device__ __forceinline__ void epilogue_bf16(float acc[2][8][4], const float* sB,
                                              bf16* dst, int tid) {
    int w = tid >> 5, lane = tid & 31;
    int wm = w >> 2, wn = w & 3;
    int r0 = wm * 32 + (lane >> 2);
    int cb0 = wn * 64 + 2 * (lane & 3);
#pragma unroll
    for (int m = 0; m < 2; m++) {
        int row = r0 + m * 16;
#pragma unroll
        for (int n = 0; n < 8; n++) {
            int cb = cb0 + (n >> 1) * 16 + (n & 1) * 8;
            float bx = sB[cb], by = sB[cb + 1];
            *(uint32_t*)(dst + (size_t)row * 256 + cb) =
                packbf(acc[m][n][0] + bx, acc[m][n][1] + by);
            *(uint32_t*)(dst + (size_t)(row + 8) * 256 + cb) =
                packbf(acc[m][n][2] + bx, acc[m][n][3] + by);
        }
    }
}

// ---- merged Q + K/V projection ----------------------------------------------
__global__ void __launch_bounds__(256, 2)
qkvproj_kernel(const float* img, const float* lnw, const float* lnb,
               const float* bq, const float* bk, const float* bv) {
    extern __shared__ char smem[];
    bf16*  As  = (bf16*)smem;
    bf16*  Ws0 = (bf16*)(smem + 33792);
    bf16*  Ws1 = (bf16*)(smem + 67584);
    float* lw  = (float*)(smem + 101376);
    float* lb  = (float*)(smem + 102400);
    float* sB  = (float*)(smem + 103424);
    float* Xf  = (float*)(smem + 33792);       // overlays Ws0 (Q path LN stage)

    int tid = threadIdx.x, blk = blockIdx.x;
    int w = tid >> 5, lane = tid & 31;

    if (blk < 1024) {
        int b = blk >> 6, s0 = (blk & 63) << 6;
        issue_wchunk(Ws1, g_wq, 0, tid); CP_COMMIT();
        lw[tid] = lnw[tid]; lb[tid] = lnb[tid]; sB[tid] = bq[tid];

        for (int g = 0; g < 2; g++) {
            for (int i = 0; i < 32; i++) {
                int c = w + 8 * i;
                Xf[lane * 261 + c] = img[((size_t)(b * 256 + c)) * 4096 + s0 + g * 32 + lane];
            }
            __syncthreads();
            for (int j = 0; j < 4; j++) {
                int rl = w * 4 + j;
                float v[8], s = 0.f, s2 = 0.f;
#pragma unroll
                for (int i = 0; i < 8; i++) {
                    v[i] = Xf[rl * 261 + lane + 32 * i];
                    s += v[i]; s2 += v[i] * v[i];
                }
#pragma unroll
                for (int o = 16; o; o >>= 1) {
                    s  += __shfl_xor_sync(~0u, s,  o);
                    s2 += __shfl_xor_sync(~0u, s2, o);
                }
                float mu = s * (1.f / 256.f);
                float rs = rsqrtf(s2 * (1.f / 256.f) - mu * mu + 1e-5f);
                int R = g * 32 + rl;
#pragma unroll
                for (int i = 0; i < 8; i++) {
                    int c = lane + 32 * i;
                    As[R * 264 + c] = __float2bfloat16((v[i] - mu) * rs * lw[c] + lb[c]);
                }
            }
            __syncthreads();
        }

        float acc[2][8][4];
#pragma unroll
        for (int m = 0; m < 2; m++)
#pragma unroll
            for (int n = 0; n < 8; n++)
#pragma unroll
                for (int q = 0; q < 4; q++) acc[m][n][q] = 0.f;
        mma_gemm64(smem_u32(As), Ws0, Ws1, g_wq, tid, acc);
        epilogue_bf16(acc, sB, g_q + (size_t)blk * 64 * 256, tid);
    } else {
        int blk2 = blk - 1024;
        int which = blk2 >> 6, chunk = blk2 & 63;
        const bf16* Wg = which ? g_wv : g_wk;
        issue_wchunk(Ws1, Wg, 0, tid);
        issue_tile64(As, g_kn + (size_t)chunk * 64 * 256, tid);
        CP_COMMIT();
        sB[tid] = which ? bv[tid] : bk[tid];

        float acc[2][8][4];
#pragma unroll
        for (int m = 0; m < 2; m++)
#pragma unroll
            for (int n = 0; n < 8; n++)
#pragma unroll
                for (int q = 0; q < 4; q++) acc[m][n][q] = 0.f;
        mma_gemm64(smem_u32(As), Ws0, Ws1, Wg, tid, acc);
        epilogue_bf16(acc, sB, (which ? g_v : g_k) + (size_t)chunk * 64 * 256, tid);
    }
}

// ------- flash attention: 256 q/block, 32-row warp tiles, 2 CTAs/SM ----------
// K double-buffer removed (reg diet); occupancy hides ldsm latency instead.
// smem: Ks[256][72] 36864 | Vs[256][72] 36864@36864 | B2[256] 1024@73728 = 74752
__global__ void __launch_bounds__(256, 2) attn_kernel() {
    extern __shared__ char smem[];
    bf16*  Ks = (bf16*)smem;
    bf16*  Vs = (bf16*)(smem + 36864);
    float* B2 = (float*)(smem + 73728);

    int tid = threadIdx.x, w = tid >> 5, lane = tid & 31;
    int s0 = blockIdx.x * 256, h = blockIdx.y, b = blockIdx.z;

    const bf16* ksrc = g_k + ((size_t)(b * 256)) * 256 + h * 64;
    const bf16* vsrc = g_v + ((size_t)(b * 256)) * 256 + h * 64;
    for (int u = tid; u < 2048; u += 256) {
        int r = u >> 3, j = u & 7;
        *(uint4*)(Ks + r * 72 + j * 8) = *(const uint4*)(ksrc + (size_t)r * 256 + j * 8);
        *(uint4*)(Vs + r * 72 + j * 8) = *(const uint4*)(vsrc + (size_t)r * 256 + j * 8);
    }
    B2[tid] = g_kbias[b * 256 + tid] * 1.44269504f;

    int rq = lane >> 2, c0 = 2 * (lane & 3);
    uint32_t A[2][4][4];
#pragma unroll
    for (int g = 0; g < 2; g++) {
        const bf16* q0 = g_q + ((size_t)(b * 4096 + s0 + w * 32 + g * 16 + rq)) * 256 + h * 64;
        const bf16* q1 = q0 + 8 * 256;
#pragma unroll
        for (int kk = 0; kk < 4; kk++) {
            A[g][kk][0] = *(const uint32_t*)(q0 + kk * 16 + c0);
            A[g][kk][1] = *(const uint32_t*)(q1 + kk * 16 + c0);
            A[g][kk][2] = *(const uint32_t*)(q0 + kk * 16 + c0 + 8);
            A[g][kk][3] = *(const uint32_t*)(q1 + kk * 16 + c0 + 8);
        }
    }
    __syncthreads();

    uint32_t sbK = smem_u32(Ks), sbV = smem_u32(Vs);
    int nrow_off = ((lane >> 4) & 1) * 8 + (lane & 7);
    int koff     = ((lane >> 3) & 1) * 8;
    uint32_t kbaseL = sbK + (uint32_t)(nrow_off * 72 + koff) * 2;
    int krow_off = ((lane >> 3) & 1) * 8 + (lane & 7);
    int ncol_off = ((lane >> 4) & 1) * 8;
    uint32_t vbaseL = sbV + (uint32_t)(krow_off * 72 + ncol_off) * 2;

    const float SCL2 = 0.125f * 1.44269504f;
    float O[2][8][4];
#pragma unroll
    for (int g = 0; g < 2; g++)
#pragma unroll
        for (int t = 0; t < 8; t++)
#pragma unroll
            for (int q = 0; q < 4; q++) O[g][t][q] = 0.f;
    float l0[2] = {0.f, 0.f}, l1[2] = {0.f, 0.f};

    uint32_t pa[2][4];
#pragma unroll
    for (int s = 0; s < 16; s++) {
        int kb0 = s * 16;
        uint32_t kb[4][4];
#pragma unroll
        for (int kk = 0; kk < 4; kk++)
            ldsm4(kb[kk], kbaseL + (uint32_t)((kb0 * 72 + kk * 16) * 2));
        float S[2][2][4];
#pragma unroll
        for (int g = 0; g < 2; g++) {
#pragma unroll
            for (int q = 0; q < 4; q++) { S[g][0][q] = 0.f; S[g][1][q] = 0.f; }
#pragma unroll
            for (int kk = 0; kk < 4; kk++) {
                mma16816(S[g][0], A[g][kk], kb[kk]);
                mma16816(S[g][1], A[g][kk], kb[kk] + 2);
            }
        }
        float2 bb0 = *(float2*)&B2[kb0 + c0];
        float2 bb1 = *(float2*)&B2[kb0 + 8 + c0];
#pragma unroll
        for (int g = 0; g < 2; g++) {
            float p0a = ex2(fmaf(S[g][0][0], SCL2, bb0.x));
            float p1a = ex2(fmaf(S[g][0][1], SCL2, bb0.y));
            float p2a = ex2(fmaf(S[g][0][2], SCL2, bb0.x));
            float p3a = ex2(fmaf(S[g][0][3], SCL2, bb0.y));
            float p0b = ex2(fmaf(S[g][1][0], SCL2, bb1.x));
            float p1b = ex2(fmaf(S[g][1][1], SCL2, bb1.y));
            float p2b = ex2(fmaf(S[g][1][2], SCL2, bb1.x));
            float p3b = ex2(fmaf(S[g][1][3], SCL2, bb1.y));
            l0[g] += p0a + p1a + p0b + p1b;
            l1[g] += p2a + p3a + p2b + p3b;
            pa[g][0] = packbf(p0a, p1a);
            pa[g][1] = packbf(p2a, p3a);
            pa[g][2] = packbf(p0b, p1b);
            pa[g][3] = packbf(p2b, p3b);
        }
#pragma unroll
        for (int nn = 0; nn < 4; nn++) {
            uint32_t vb[4];
            ldsm4t(vb, vbaseL + (uint32_t)((kb0 * 72 + nn * 16) * 2));
#pragma unroll
            for (int g = 0; g < 2; g++) {
                mma16816(O[g][2 * nn],     pa[g], vb);
                mma16816(O[g][2 * nn + 1], pa[g], vb + 2);
            }
        }
    }
#pragma unroll
    for (int g = 0; g < 2; g++) {
        float a = l0[g], c = l1[g];
        a += __shfl_xor_sync(~0u, a, 1);
        a += __shfl_xor_sync(~0u, a, 2);
        c += __shfl_xor_sync(~0u, c, 1);
        c += __shfl_xor_sync(~0u, c, 2);
        float inv0 = 1.f / a, inv1 = 1.f / c;
        bf16* o0 = g_o + ((size_t)(b * 4096 + s0 + w * 32 + g * 16 + rq)) * 256 + h * 64 + c0;
        bf16* o1 = o0 + 8 * 256;
#pragma unroll
        for (int t = 0; t < 8; t++) {
            *(uint32_t*)(o0 + t * 8) = packbf(O[g][t][0] * inv0, O[g][t][1] * inv0);
            *(uint32_t*)(o1 + t * 8) = packbf(O[g][t][2] * inv1, O[g][t][3] * inv1);
        }
    }
}

// ---- O projection + AdaLN + residual + float4 transposed epilogue -----------
__global__ void __launch_bounds__(256, 2)
oproj_kernel(const float* img, const float* bo, float* out) {
    extern __shared__ char smem[];
    bf16*  As  = (bf16*)smem;
    bf16*  Ws0 = (bf16*)(smem + 33792);
    bf16*  Ws1 = (bf16*)(smem + 67584);
    float* Md  = (float*)(smem + 101376);
    float* Bo  = (float*)(smem + 104448);
    float* stage = (float*)smem;             // [256 cols][68] post-GEMM

    int tid = threadIdx.x, blk = blockIdx.x;
    int b = blk >> 6, s0 = (blk & 63) << 6;
    int w = tid >> 5, lane = tid & 31;

    issue_wchunk(Ws1, g_wo, 0, tid);
    issue_tile64(As, g_o + (size_t)blk * 64 * 256, tid);
    CP_COMMIT();

    Md[tid]       = g_mod[b * 768 + tid];
    Md[tid + 256] = g_mod[b * 768 + tid + 256];
    Md[tid + 512] = g_mod[b * 768 + tid + 512];
    Bo[tid] = bo[tid];

    float acc[2][8][4];
#pragma unroll
    for (int m = 0; m < 2; m++)
#pragma unroll
        for (int n = 0; n < 8; n++)
#pragma unroll
            for (int q = 0; q < 4; q++) acc[m][n][q] = 0.f;

    mma_gemm64(smem_u32(As), Ws0, Ws1, g_wo, tid, acc);

    {
        int wm = w >> 2, wn = w & 3;
        int r0 = wm * 32 + (lane >> 2);
        int cb0 = wn * 64 + 2 * (lane & 3);
#pragma unroll
        for (int m = 0; m < 2; m++) {
            int row = r0 + m * 16;
#pragma unroll
            for (int n = 0; n < 8; n++) {
                int cb = cb0 + (n >> 1) * 16 + (n & 1) * 8;
                stage[cb * 68 + row]           = acc[m][n][0];
                stage[(cb + 1) * 68 + row]     = acc[m][n][1];
                stage[cb * 68 + row + 8]       = acc[m][n][2];
                stage[(cb + 1) * 68 + row + 8] = acc[m][n][3];
            }
        }
        __syncthreads();
    }

#pragma unroll
    for (int it = 0; it < 16; it++) {
        int c = w * 32 + it * 2 + (lane >> 4);
        int r4 = (lane & 15) * 4;
        float4 v = *(float4*)&stage[c * 68 + r4];
        float shift = Md[c], scv1 = 1.f + Md[c + 256], gate = Md[c + 512];
        float bias = Bo[c];
        const float4* xb = (const float4*)(img + ((size_t)(b * 256 + c)) * 4096 + s0 + r4);
        float4*       ob = (float4*)(out + ((size_t)(b * 256 + c)) * 4096 + s0 + r4);
        float4 x = *xb;
        float4 o;
        o.x = fmaf(gate, fmaf(v.x + bias, scv1, shift), x.x);
        o.y = fmaf(gate, fmaf(v.y + bias, scv1, shift), x.y);
        o.z = fmaf(gate, fmaf(v.z + bias, scv1, shift), x.z);
        o.w = fmaf(gate, fmaf(v.w + bias, scv1, shift), x.w);
        *ob = o;
    }
}

// ---------------- launcher ---------------------------------------------------
extern "C" void kernel_launch(void* const* d_in, const int* in_sizes, int n_in,
                              void* d_out, int out_size) {
    const float* img        = (const float*)d_in[0];
    const float* refs       = (const float*)d_in[1];
    const void*  masks      = d_in[2];
    const float* ref_embeds = (const float*)d_in[3];
    const float* ln_img_w   = (const float*)d_in[4];
    const float* ln_img_b   = (const float*)d_in[5];
    const float* ln_txt_w   = (const float*)d_in[6];
    const float* ln_txt_b   = (const float*)d_in[7];
    const float* Wq         = (const float*)d_in[8];
    const float* bq         = (const float*)d_in[9];
    const float* Wk         = (const float*)d_in[10];
    const float* bk         = (const float*)d_in[11];
    const float* Wv         = (const float*)d_in[12];
    const float* bv         = (const float*)d_in[13];
    const float* Wo         = (const float*)d_in[14];
    const float* bo         = (const float*)d_in[15];
    const float* Wada       = (const float*)d_in[16];
    const float* bada       = (const float*)d_in[17];
    float* out = (float*)d_out;

    cudaFuncSetAttribute(qkvproj_kernel, cudaFuncAttributeMaxDynamicSharedMemorySize, 104448);
    cudaFuncSetAttribute(attn_kernel,    cudaFuncAttributeMaxDynamicSharedMemorySize, 74752);
    cudaFuncSetAttribute(oproj_kernel,   cudaFuncAttributeMaxDynamicSharedMemorySize, 105472);

    prep_kernel<<<817, 256>>>(masks, Wq, Wk, Wv, Wo, refs, ln_txt_w, ln_txt_b,
                              ref_embeds, Wada, bada);
    qkvproj_kernel<<<1152, 256, 104448>>>(img, ln_img_w, ln_img_b, bq, bk, bv);
    attn_kernel<<<dim3(16, 4, 16), 256, 74752>>>();
    oproj_kernel<<<1024, 256, 105472>>>(img, bo, out);
}